// round 4
// baseline (speedup 1.0000x reference)
#include <cuda_runtime.h>

#define B_ROWS 512
#define S_LEN 16384
#define NTHREADS 1024
#define TPT 16   // tokens per thread: 1024 * 16 = 16384 = S_LEN

// -------- global accumulators (device scratch; no allocation allowed) --------
__device__ unsigned long long g_n;      // number of valid time gaps (N)
__device__ unsigned long long g_sumd;   // sum of gaps
__device__ unsigned long long g_sumd2;  // sum of squared gaps
__device__ unsigned long long g_harm;   // tritone pair count
__device__ unsigned long long g_leaps;  // voice leap count
__device__ int g_is64;                  // input dtype flag

// -------- zero accumulators + detect int64 vs int32 input --------
__global__ void zero_detect_kernel(const void* __restrict__ in) {
    if (threadIdx.x == 0 && blockIdx.x == 0) {
        g_n = 0ULL; g_sumd = 0ULL; g_sumd2 = 0ULL; g_harm = 0ULL; g_leaps = 0ULL;
        // If the buffer is int64, every 8-byte word is a token in [0, 774).
        // If it is int32, an 8-byte read combines two tokens -> value >= 2^32
        // unless the odd token is 0 (prob ~(1/774)^16 across 16 words; never
        // for this fixed random input).
        const long long* p = (const long long*)in;
        int ok = 1;
        #pragma unroll
        for (int i = 0; i < 16; i++) {
            long long v = p[i];
            if (v < 0 || v >= 1024) ok = 0;
        }
        g_is64 = ok;
    }
}

struct Smem {
    int sT[NTHREADS];   // scan: last time-token position per thread
    int sN[NTHREADS];   // scan: last note-token value per thread
    int sF[NTHREADS];   // first token value per thread (harmony boundary)
    int rC[32], rS[32], rL[32], rH[32], rMn[32], rMx[32];
};

template <bool IS64>
__device__ __forceinline__ void row_impl(const void* __restrict__ in, Smem* sm) {
    const int row = blockIdx.x;
    const int tid = threadIdx.x;
    const long long base = (long long)row * S_LEN + (long long)tid * TPT;

    // ---- load 16 tokens (8x LDG.128 for int64 -> high MLP) ----
    int t[TPT];
    if (IS64) {
        const longlong2* p = (const longlong2*)((const long long*)in + base);
        #pragma unroll
        for (int i = 0; i < TPT / 2; i++) {
            longlong2 v = p[i];
            t[2 * i]     = (int)v.x;
            t[2 * i + 1] = (int)v.y;
        }
    } else {
        const int4* p = (const int4*)((const int*)in + base);
        #pragma unroll
        for (int i = 0; i < TPT / 4; i++) {
            int4 v = p[i];
            t[4 * i] = v.x; t[4 * i + 1] = v.y; t[4 * i + 2] = v.z; t[4 * i + 3] = v.w;
        }
    }

    // ---- thread-local sequential pass over 16 tokens ----
    const int pbase = tid * TPT;
    int firstT = -1, lastT = -1, cntT = 0;   // time tokens: positions
    int firstN = -1, lastN = -1;             // note tokens: values
    int sumd2 = 0, leaps = 0, harm = 0;
    int prevPc = 0;
    bool prevNote = false;

    #pragma unroll
    for (int j = 0; j < TPT; j++) {
        int v = t[j];
        int p = pbase + j;
        bool nt = (unsigned)v < 128u;                  // note_on token
        bool tm = (unsigned)(v - 256) < 512u;          // time_shift token
        int pc = (int)((unsigned)v % 12u);             // pitch class
        if (tm) {
            if (lastT >= 0) { int d = p - lastT; sumd2 += d * d; }
            else            { firstT = p; }
            lastT = p;
            cntT++;
        }
        if (nt) {
            if (lastN >= 0) { int iv = v - lastN; leaps += (iv > 12) || (iv < -12); }
            else            { firstN = v; }
            lastN = v;
            if (prevNote) {
                int dpc = pc - prevPc;
                harm += (dpc == 6) || (dpc == -6);
            }
        }
        prevNote = nt;
        prevPc = pc;
    }

    // ---- block-level "last valid" exclusive scan (Hillis-Steele) ----
    sm->sT[tid] = lastT;
    sm->sN[tid] = lastN;
    sm->sF[tid] = t[0];
    __syncthreads();

    int vt = lastT, vn = lastN;
    #pragma unroll
    for (int off = 1; off < NTHREADS; off <<= 1) {
        int ot = -1, on = -1;
        if (tid >= off) { ot = sm->sT[tid - off]; on = sm->sN[tid - off]; }
        __syncthreads();
        if (vt < 0) vt = ot;
        if (vn < 0) vn = on;
        sm->sT[tid] = vt;
        sm->sN[tid] = vn;
        __syncthreads();
    }
    int exT = (tid > 0) ? sm->sT[tid - 1] : -1;   // last time pos before my chunk
    int exN = (tid > 0) ? sm->sN[tid - 1] : -1;   // last note val before my chunk

    // ---- cross-thread boundary contributions ----
    if (firstT >= 0 && exT >= 0) { int d = firstT - exT; sumd2 += d * d; }
    if (firstN >= 0 && exN >= 0) { int iv = firstN - exN; leaps += (iv > 12) || (iv < -12); }
    if (tid < NTHREADS - 1) {
        int nv = sm->sF[tid + 1];  // first token of next thread
        if (prevNote && (unsigned)nv < 128u) {
            int dpc = (int)((unsigned)nv % 12u) - prevPc;
            harm += (dpc == 6) || (dpc == -6);
        }
    }

    // ---- block reduction ----
    int mnF = (firstT < 0) ? 0x7fffffff : firstT;
    int mxL = lastT;  // -1 sentinel is fine for max
    const unsigned FULL = 0xffffffffu;
    #pragma unroll
    for (int off = 16; off > 0; off >>= 1) {
        cntT  += __shfl_down_sync(FULL, cntT,  off);
        sumd2 += __shfl_down_sync(FULL, sumd2, off);
        leaps += __shfl_down_sync(FULL, leaps, off);
        harm  += __shfl_down_sync(FULL, harm,  off);
        mnF = min(mnF, __shfl_down_sync(FULL, mnF, off));
        mxL = max(mxL, __shfl_down_sync(FULL, mxL, off));
    }
    int wid = tid >> 5, lid = tid & 31;
    if (lid == 0) {
        sm->rC[wid] = cntT;  sm->rS[wid] = sumd2; sm->rL[wid] = leaps;
        sm->rH[wid] = harm;  sm->rMn[wid] = mnF;  sm->rMx[wid] = mxL;
    }
    __syncthreads();
    if (wid == 0) {
        cntT  = sm->rC[lid];  sumd2 = sm->rS[lid]; leaps = sm->rL[lid];
        harm  = sm->rH[lid];  mnF   = sm->rMn[lid]; mxL  = sm->rMx[lid];
        #pragma unroll
        for (int off = 16; off > 0; off >>= 1) {
            cntT  += __shfl_down_sync(FULL, cntT,  off);
            sumd2 += __shfl_down_sync(FULL, sumd2, off);
            leaps += __shfl_down_sync(FULL, leaps, off);
            harm  += __shfl_down_sync(FULL, harm,  off);
            mnF = min(mnF, __shfl_down_sync(FULL, mnF, off));
            mxL = max(mxL, __shfl_down_sync(FULL, mxL, off));
        }
        if (lid == 0) {
            int n_row = cntT > 1 ? (cntT - 1) : 0;
            int sumd_row = (cntT >= 2) ? (mxL - mnF) : 0;
            atomicAdd(&g_n,     (unsigned long long)n_row);
            atomicAdd(&g_sumd,  (unsigned long long)sumd_row);
            atomicAdd(&g_sumd2, (unsigned long long)(unsigned int)sumd2);
            atomicAdd(&g_harm,  (unsigned long long)harm);
            atomicAdd(&g_leaps, (unsigned long long)leaps);
        }
    }
}

__global__ void __launch_bounds__(NTHREADS, 1)
row_kernel(const void* __restrict__ in) {
    __shared__ Smem sm;
    if (g_is64) row_impl<true>(in, &sm);
    else        row_impl<false>(in, &sm);
}

__global__ void finalize_kernel(float* __restrict__ out) {
    if (threadIdx.x == 0 && blockIdx.x == 0) {
        double N     = (double)g_n;
        double sumd  = (double)g_sumd;
        double sumd2 = (double)g_sumd2;
        double mean  = sumd / (N > 1.0 ? N : 1.0);
        double ss    = sumd2 - 2.0 * mean * sumd + N * mean * mean;
        double var   = (N > 1.0) ? (ss / (N - 1.0)) : 0.0;
        float rhythm  = (float)(var * 0.01);
        float harmony = (float)(0.1 * (double)g_harm / (double)((long long)B_ROWS * S_LEN));
        float voice   = (float)((double)g_leaps / (double)B_ROWS);
        float total   = rhythm + harmony + 0.5f * voice;
        out[0] = rhythm; out[1] = harmony; out[2] = voice; out[3] = total;
    }
}

extern "C" void kernel_launch(void* const* d_in, const int* in_sizes, int n_in,
                              void* d_out, int out_size) {
    const void* in = d_in[0];
    zero_detect_kernel<<<1, 32>>>(in);
    row_kernel<<<B_ROWS, NTHREADS>>>(in);
    finalize_kernel<<<1, 32>>>((float*)d_out);
}